// round 2
// baseline (speedup 1.0000x reference)
#include <cuda_runtime.h>

#define BB 64
#define SS 1024
#define DD 16

// Scratch (allocation-free rule: __device__ globals)
__device__ float4 g_kv[BB * SS];   // (k0, k1, v0, v1) per (b,t)
__device__ float2 g_q[BB * SS];    // q pre-scaled by 0.25 * log2(e)
__device__ float2 g_ctx[BB * SS];  // attention context (c0, c1)

__device__ __forceinline__ float ex2_approx(float x) {
    float y;
    asm("ex2.approx.f32 %0, %1;" : "=f"(y) : "f"(x));
    return y;
}

// ---------------------------------------------------------------------------
// Kernel 1: QKV projection.  One thread per (b,s) token.
// ---------------------------------------------------------------------------
__global__ void qkv_kernel(const float* __restrict__ x,
                           const float* __restrict__ Wq, const float* __restrict__ bq,
                           const float* __restrict__ Wk, const float* __restrict__ bk,
                           const float* __restrict__ Wv, const float* __restrict__ bv)
{
    __shared__ float sw[102];  // Wq[32] Wk[32] Wv[32] bq[2] bk[2] bv[2]
    int tid = threadIdx.x;
    if (tid < 32)        sw[tid] = Wq[tid];
    else if (tid < 64)   sw[tid] = Wk[tid - 32];
    else if (tid < 96)   sw[tid] = Wv[tid - 64];
    else if (tid < 98)   sw[tid] = bq[tid - 96];
    else if (tid < 100)  sw[tid] = bk[tid - 98];
    else if (tid < 102)  sw[tid] = bv[tid - 100];
    __syncthreads();

    int idx = blockIdx.x * blockDim.x + tid;   // b*S + s
    const float4* xp = reinterpret_cast<const float4*>(x + idx * DD);
    float xv[16];
    #pragma unroll
    for (int c = 0; c < 4; c++) {
        float4 v = xp[c];
        xv[4*c+0] = v.x; xv[4*c+1] = v.y; xv[4*c+2] = v.z; xv[4*c+3] = v.w;
    }

    float q0 = sw[96], q1 = sw[97];
    float k0 = sw[98], k1 = sw[99];
    float v0 = sw[100], v1 = sw[101];
    #pragma unroll
    for (int i = 0; i < 16; i++) {
        float xi = xv[i];
        q0 = fmaf(xi, sw[i*2+0],    q0);
        q1 = fmaf(xi, sw[i*2+1],    q1);
        k0 = fmaf(xi, sw[32+i*2+0], k0);
        k1 = fmaf(xi, sw[32+i*2+1], k1);
        v0 = fmaf(xi, sw[64+i*2+0], v0);
        v1 = fmaf(xi, sw[64+i*2+1], v1);
    }

    // Fold softmax scale (0.25) and log2(e) into Q: inner loop = dot -> ex2.
    const float SC = 0.25f * 1.4426950408889634f;
    g_q[idx]  = make_float2(q0 * SC, q1 * SC);
    g_kv[idx] = make_float4(k0, k1, v0, v1);
}

// ---------------------------------------------------------------------------
// Kernel 2: attention, 4-way split-KV within the warp.
// Block = 256 threads = 64 tokens x 4 splits; lanes 4k..4k+3 share token k.
// Grid = (S/64, B) = (16, 64) -> 262144 threads (~87% occupancy ceiling).
// ---------------------------------------------------------------------------
__global__ void __launch_bounds__(256)
attn_kernel()
{
    __shared__ float4 skv[SS];   // 16 KB: whole batch-row KV

    int tid   = threadIdx.x;
    int b     = blockIdx.y;
    int s     = blockIdx.x * 64 + (tid >> 2);
    int split = tid & 3;

    const float4* kvsrc = g_kv + b * SS;
    #pragma unroll
    for (int i = 0; i < 4; i++) skv[tid + i * 256] = kvsrc[tid + i * 256];
    __syncthreads();

    float2 q = g_q[b * SS + s];
    float l = 0.f, a0 = 0.f, a1 = 0.f;
    const float4* kp = skv + split * 256;

    #pragma unroll 8
    for (int t = 0; t < 256; t++) {
        float4 kv = kp[t];
        float d = fmaf(q.y, kv.y, q.x * kv.x);   // log2-domain score
        float p = ex2_approx(d);
        l  += p;
        a0 = fmaf(p, kv.z, a0);
        a1 = fmaf(p, kv.w, a1);
    }

    // Reduce across the 4 splits (adjacent lanes)
    l  += __shfl_xor_sync(0xFFFFFFFFu, l, 1);
    a0 += __shfl_xor_sync(0xFFFFFFFFu, a0, 1);
    a1 += __shfl_xor_sync(0xFFFFFFFFu, a1, 1);
    l  += __shfl_xor_sync(0xFFFFFFFFu, l, 2);
    a0 += __shfl_xor_sync(0xFFFFFFFFu, a0, 2);
    a1 += __shfl_xor_sync(0xFFFFFFFFu, a1, 2);

    if (split == 0) {
        float inv = 1.0f / l;
        g_ctx[b * SS + s] = make_float2(a0 * inv, a1 * inv);
    }
}

// ---------------------------------------------------------------------------
// 16x16 dense matmul from SMEM weights (row-major)
// ---------------------------------------------------------------------------
__device__ __forceinline__ void mm16(const float* __restrict__ in,
                                     const float* __restrict__ Ws,
                                     const float* __restrict__ bs,
                                     float* __restrict__ outr)
{
    float acc[16];
    #pragma unroll
    for (int j = 0; j < 16; j++) acc[j] = bs[j];
    #pragma unroll
    for (int i = 0; i < 16; i++) {
        float hv = in[i];
        const float4* wr = reinterpret_cast<const float4*>(Ws + i * 16);
        #pragma unroll
        for (int j = 0; j < 4; j++) {
            float4 w = wr[j];
            acc[4*j+0] = fmaf(hv, w.x, acc[4*j+0]);
            acc[4*j+1] = fmaf(hv, w.y, acc[4*j+1]);
            acc[4*j+2] = fmaf(hv, w.z, acc[4*j+2]);
            acc[4*j+3] = fmaf(hv, w.w, acc[4*j+3]);
        }
    }
    #pragma unroll
    for (int j = 0; j < 16; j++) outr[j] = acc[j];
}

__device__ __forceinline__ void layernorm16(float* __restrict__ v,
                                            const float* __restrict__ g,
                                            const float* __restrict__ b)
{
    float mu = 0.f;
    #pragma unroll
    for (int j = 0; j < 16; j++) mu += v[j];
    mu *= (1.0f / 16.0f);
    float var = 0.f;
    #pragma unroll
    for (int j = 0; j < 16; j++) { float d = v[j] - mu; var = fmaf(d, d, var); }
    var *= (1.0f / 16.0f);
    float r = rsqrtf(var + 1e-5f);
    #pragma unroll
    for (int j = 0; j < 16; j++) v[j] = fmaf((v[j] - mu) * r, g[j], b[j]);
}

// ---------------------------------------------------------------------------
// Kernel 3: epilogue.  One thread per token: Wu + residual + LN + FF + LN + Wo
// ---------------------------------------------------------------------------
__global__ void __launch_bounds__(128)
epilogue_kernel(const float* __restrict__ x,
                const float* __restrict__ Wu, const float* __restrict__ bu,
                const float* __restrict__ ln_g, const float* __restrict__ ln_b,
                const float* __restrict__ W1, const float* __restrict__ b1,
                const float* __restrict__ W2, const float* __restrict__ b2,
                const float* __restrict__ W3, const float* __restrict__ b3,
                const float* __restrict__ Wo, const float* __restrict__ bo,
                float* __restrict__ out)
{
    __shared__ __align__(16) float sW1[256], sW2[256], sW3[256], sWo[256];
    __shared__ __align__(16) float sWu[32];
    __shared__ float sbu[16], sg[16], sb[16], sb1[16], sb2[16], sb3[16], sbo[16];

    int tid = threadIdx.x;
    int idx = blockIdx.x * 128 + tid;   // b*S + s

    for (int i = tid; i < 256; i += 128) {
        sW1[i] = W1[i]; sW2[i] = W2[i]; sW3[i] = W3[i]; sWo[i] = Wo[i];
    }
    if (tid < 32) sWu[tid] = Wu[tid];
    if (tid < 16) {
        sbu[tid] = bu[tid]; sg[tid] = ln_g[tid]; sb[tid] = ln_b[tid];
        sb1[tid] = b1[tid]; sb2[tid] = b2[tid];  sb3[tid] = b3[tid];
        sbo[tid] = bo[tid];
    }
    __syncthreads();

    float2 c = g_ctx[idx];

    float xr[16];
    const float4* xp = reinterpret_cast<const float4*>(x + idx * DD);
    #pragma unroll
    for (int ci = 0; ci < 4; ci++) {
        float4 v = xp[ci];
        xr[4*ci+0] = v.x; xr[4*ci+1] = v.y; xr[4*ci+2] = v.z; xr[4*ci+3] = v.w;
    }

    float h[16];
    #pragma unroll
    for (int j = 0; j < 16; j++)
        h[j] = fmaf(c.x, sWu[j], fmaf(c.y, sWu[16 + j], sbu[j])) + xr[j];

    layernorm16(h, sg, sb);

    float t1[16], t2[16], t3[16];
    mm16(h,  sW1, sb1, t1);
    mm16(t1, sW2, sb2, t2);
    mm16(t2, sW3, sb3, t3);
    #pragma unroll
    for (int j = 0; j < 16; j++) t3[j] += h[j];

    layernorm16(t3, sg, sb);

    float o[16];
    mm16(t3, sWo, sbo, o);

    float4* op = reinterpret_cast<float4*>(out + idx * DD);
    #pragma unroll
    for (int ci = 0; ci < 4; ci++)
        op[ci] = make_float4(o[4*ci+0], o[4*ci+1], o[4*ci+2], o[4*ci+3]);
}

// ---------------------------------------------------------------------------
extern "C" void kernel_launch(void* const* d_in, const int* in_sizes, int n_in,
                              void* d_out, int out_size)
{
    const float* x    = (const float*)d_in[0];
    const float* Wq   = (const float*)d_in[1];
    const float* bq   = (const float*)d_in[2];
    const float* Wk   = (const float*)d_in[3];
    const float* bk   = (const float*)d_in[4];
    const float* Wv   = (const float*)d_in[5];
    const float* bv   = (const float*)d_in[6];
    const float* Wu   = (const float*)d_in[7];
    const float* bu   = (const float*)d_in[8];
    const float* ln_g = (const float*)d_in[9];
    const float* ln_b = (const float*)d_in[10];
    const float* W1   = (const float*)d_in[11];
    const float* b1   = (const float*)d_in[12];
    const float* W2   = (const float*)d_in[13];
    const float* b2   = (const float*)d_in[14];
    const float* W3   = (const float*)d_in[15];
    const float* b3   = (const float*)d_in[16];
    const float* Wo   = (const float*)d_in[17];
    const float* bo   = (const float*)d_in[18];
    float* out = (float*)d_out;

    qkv_kernel<<<(BB * SS) / 256, 256>>>(x, Wq, bq, Wk, bk, Wv, bv);

    dim3 agrid(SS / 64, BB);
    attn_kernel<<<agrid, 256>>>();

    epilogue_kernel<<<(BB * SS) / 128, 128>>>(x, Wu, bu, ln_g, ln_b,
                                              W1, b1, W2, b2, W3, b3, Wo, bo, out);
}

// round 3
// speedup vs baseline: 3.4916x; 3.4916x over previous
#include <cuda_runtime.h>

#define BB 64
#define SS 1024
#define DD 16

// Scratch (allocation-free rule: __device__ globals)
__device__ float4 g_kv[BB * SS];   // (k0, k1, v0, v1) per (b,t)
__device__ float2 g_q[BB * SS];    // q pre-scaled by 0.25 * log2(e)
__device__ float2 g_ctx[BB * SS];  // attention context (c0, c1)

__device__ __forceinline__ float ex2_approx(float x) {
    float y;
    asm("ex2.approx.f32 %0, %1;" : "=f"(y) : "f"(x));
    return y;
}

// ---------------------------------------------------------------------------
// Kernel 1: QKV projection, split by role.
// g = global thread id; role = g>>16 (0=q,1=k,2=v); token = g & 0xFFFF.
// 196608 threads, 32 FMA each -> latency-bound time / 3 vs R1 version.
// ---------------------------------------------------------------------------
__global__ void __launch_bounds__(256)
qkv_kernel(const float* __restrict__ x,
           const float* __restrict__ Wq, const float* __restrict__ bq,
           const float* __restrict__ Wk, const float* __restrict__ bk,
           const float* __restrict__ Wv, const float* __restrict__ bv)
{
    __shared__ float sw[102];  // [0:32) Wq [32:64) Wk [64:96) Wv [96:102) bq,bk,bv
    int tid = threadIdx.x;
    if (tid < 32)        sw[tid] = Wq[tid];
    else if (tid < 64)   sw[tid] = Wk[tid - 32];
    else if (tid < 96)   sw[tid] = Wv[tid - 64];
    else if (tid < 98)   sw[tid] = bq[tid - 96];
    else if (tid < 100)  sw[tid] = bk[tid - 98];
    else if (tid < 102)  sw[tid] = bv[tid - 100];
    __syncthreads();

    int g    = blockIdx.x * 256 + tid;
    int role = g >> 16;            // 0..2 (grid sized exactly 3*65536/256)
    int idx  = g & 0xFFFF;         // b*S + s

    const float4* xp = reinterpret_cast<const float4*>(x + idx * DD);
    float xv[16];
    #pragma unroll
    for (int c = 0; c < 4; c++) {
        float4 v = xp[c];
        xv[4*c+0] = v.x; xv[4*c+1] = v.y; xv[4*c+2] = v.z; xv[4*c+3] = v.w;
    }

    const float* W = sw + role * 32;
    float a0 = sw[96 + role * 2];
    float a1 = sw[97 + role * 2];
    #pragma unroll
    for (int i = 0; i < 16; i++) {
        a0 = fmaf(xv[i], W[i*2+0], a0);
        a1 = fmaf(xv[i], W[i*2+1], a1);
    }

    const float SC = 0.25f * 1.4426950408889634f;  // fold scale + log2(e) into Q
    if (role == 0) {
        g_q[idx] = make_float2(a0 * SC, a1 * SC);
    } else {
        reinterpret_cast<float2*>(g_kv)[idx * 2 + (role - 1)] = make_float2(a0, a1);
    }
}

// ---------------------------------------------------------------------------
// Kernel 2: attention, 2-way INTERLEAVED split-KV.
// Block = 256 threads = 128 tokens x 2 splits; thread handles t = 2i + split.
// Warp reads skv[2i], skv[2i+1]: 2 consecutive float4 -> conflict-free,
// 16-way broadcast each (preserves R1's cheap-LDS property).
// ---------------------------------------------------------------------------
__global__ void __launch_bounds__(256)
attn_kernel()
{
    __shared__ float4 skv[SS];   // 16 KB

    int tid   = threadIdx.x;
    int b     = blockIdx.y;
    int s     = blockIdx.x * 128 + (tid >> 1);
    int split = tid & 1;

    const float4* kvsrc = g_kv + b * SS;
    #pragma unroll
    for (int i = 0; i < 4; i++) skv[tid + i * 256] = kvsrc[tid + i * 256];
    __syncthreads();

    float2 q = g_q[b * SS + s];
    float l = 0.f, a0 = 0.f, a1 = 0.f;

    #pragma unroll 8
    for (int i = 0; i < 512; i++) {
        float4 kv = skv[2 * i + split];
        float d = fmaf(q.y, kv.y, q.x * kv.x);   // log2-domain score
        float p = ex2_approx(d);
        l  += p;
        a0 = fmaf(p, kv.z, a0);
        a1 = fmaf(p, kv.w, a1);
    }

    // Combine the 2 splits (adjacent lanes)
    l  += __shfl_xor_sync(0xFFFFFFFFu, l, 1);
    a0 += __shfl_xor_sync(0xFFFFFFFFu, a0, 1);
    a1 += __shfl_xor_sync(0xFFFFFFFFu, a1, 1);

    if (split == 0) {
        float inv = 1.0f / l;
        g_ctx[b * SS + s] = make_float2(a0 * inv, a1 * inv);
    }
}

// ---------------------------------------------------------------------------
// 16x16 dense matmul from SMEM weights (row-major)
// ---------------------------------------------------------------------------
__device__ __forceinline__ void mm16(const float* __restrict__ in,
                                     const float* __restrict__ Ws,
                                     const float* __restrict__ bs,
                                     float* __restrict__ outr)
{
    float acc[16];
    #pragma unroll
    for (int j = 0; j < 16; j++) acc[j] = bs[j];
    #pragma unroll
    for (int i = 0; i < 16; i++) {
        float hv = in[i];
        const float4* wr = reinterpret_cast<const float4*>(Ws + i * 16);
        #pragma unroll
        for (int j = 0; j < 4; j++) {
            float4 w = wr[j];
            acc[4*j+0] = fmaf(hv, w.x, acc[4*j+0]);
            acc[4*j+1] = fmaf(hv, w.y, acc[4*j+1]);
            acc[4*j+2] = fmaf(hv, w.z, acc[4*j+2]);
            acc[4*j+3] = fmaf(hv, w.w, acc[4*j+3]);
        }
    }
    #pragma unroll
    for (int j = 0; j < 16; j++) outr[j] = acc[j];
}

__device__ __forceinline__ void layernorm16(float* __restrict__ v,
                                            const float* __restrict__ g,
                                            const float* __restrict__ b)
{
    float mu = 0.f;
    #pragma unroll
    for (int j = 0; j < 16; j++) mu += v[j];
    mu *= (1.0f / 16.0f);
    float var = 0.f;
    #pragma unroll
    for (int j = 0; j < 16; j++) { float d = v[j] - mu; var = fmaf(d, d, var); }
    var *= (1.0f / 16.0f);
    float r = rsqrtf(var + 1e-5f);
    #pragma unroll
    for (int j = 0; j < 16; j++) v[j] = fmaf((v[j] - mu) * r, g[j], b[j]);
}

// ---------------------------------------------------------------------------
// Kernel 3: epilogue. One thread per token: Wu + residual + LN + FF + LN + Wo
// ---------------------------------------------------------------------------
__global__ void __launch_bounds__(128)
epilogue_kernel(const float* __restrict__ x,
                const float* __restrict__ Wu, const float* __restrict__ bu,
                const float* __restrict__ ln_g, const float* __restrict__ ln_b,
                const float* __restrict__ W1, const float* __restrict__ b1,
                const float* __restrict__ W2, const float* __restrict__ b2,
                const float* __restrict__ W3, const float* __restrict__ b3,
                const float* __restrict__ Wo, const float* __restrict__ bo,
                float* __restrict__ out)
{
    __shared__ __align__(16) float sW1[256], sW2[256], sW3[256], sWo[256];
    __shared__ __align__(16) float sWu[32];
    __shared__ float sbu[16], sg[16], sb[16], sb1[16], sb2[16], sb3[16], sbo[16];

    int tid = threadIdx.x;
    int idx = blockIdx.x * 128 + tid;   // b*S + s

    for (int i = tid; i < 256; i += 128) {
        sW1[i] = W1[i]; sW2[i] = W2[i]; sW3[i] = W3[i]; sWo[i] = Wo[i];
    }
    if (tid < 32) sWu[tid] = Wu[tid];
    if (tid < 16) {
        sbu[tid] = bu[tid]; sg[tid] = ln_g[tid]; sb[tid] = ln_b[tid];
        sb1[tid] = b1[tid]; sb2[tid] = b2[tid];  sb3[tid] = b3[tid];
        sbo[tid] = bo[tid];
    }
    __syncthreads();

    float2 c = g_ctx[idx];

    float xr[16];
    const float4* xp = reinterpret_cast<const float4*>(x + idx * DD);
    #pragma unroll
    for (int ci = 0; ci < 4; ci++) {
        float4 v = xp[ci];
        xr[4*ci+0] = v.x; xr[4*ci+1] = v.y; xr[4*ci+2] = v.z; xr[4*ci+3] = v.w;
    }

    float h[16];
    #pragma unroll
    for (int j = 0; j < 16; j++)
        h[j] = fmaf(c.x, sWu[j], fmaf(c.y, sWu[16 + j], sbu[j])) + xr[j];

    layernorm16(h, sg, sb);

    float t1[16], t2[16], t3[16];
    mm16(h,  sW1, sb1, t1);
    mm16(t1, sW2, sb2, t2);
    mm16(t2, sW3, sb3, t3);
    #pragma unroll
    for (int j = 0; j < 16; j++) t3[j] += h[j];

    layernorm16(t3, sg, sb);

    float o[16];
    mm16(t3, sWo, sbo, o);

    float4* op = reinterpret_cast<float4*>(out + idx * DD);
    #pragma unroll
    for (int ci = 0; ci < 4; ci++)
        op[ci] = make_float4(o[4*ci+0], o[4*ci+1], o[4*ci+2], o[4*ci+3]);
}

// ---------------------------------------------------------------------------
extern "C" void kernel_launch(void* const* d_in, const int* in_sizes, int n_in,
                              void* d_out, int out_size)
{
    const float* x    = (const float*)d_in[0];
    const float* Wq   = (const float*)d_in[1];
    const float* bq   = (const float*)d_in[2];
    const float* Wk   = (const float*)d_in[3];
    const float* bk   = (const float*)d_in[4];
    const float* Wv   = (const float*)d_in[5];
    const float* bv   = (const float*)d_in[6];
    const float* Wu   = (const float*)d_in[7];
    const float* bu   = (const float*)d_in[8];
    const float* ln_g = (const float*)d_in[9];
    const float* ln_b = (const float*)d_in[10];
    const float* W1   = (const float*)d_in[11];
    const float* b1   = (const float*)d_in[12];
    const float* W2   = (const float*)d_in[13];
    const float* b2   = (const float*)d_in[14];
    const float* W3   = (const float*)d_in[15];
    const float* b3   = (const float*)d_in[16];
    const float* Wo   = (const float*)d_in[17];
    const float* bo   = (const float*)d_in[18];
    float* out = (float*)d_out;

    qkv_kernel<<<(3 * BB * SS) / 256, 256>>>(x, Wq, bq, Wk, bk, Wv, bv);

    dim3 agrid(SS / 128, BB);
    attn_kernel<<<agrid, 256>>>();

    epilogue_kernel<<<(BB * SS) / 128, 128>>>(x, Wu, bu, ln_g, ln_b,
                                              W1, b1, W2, b2, W3, b3, Wo, bo, out);
}

// round 4
// speedup vs baseline: 3.8656x; 1.1071x over previous
#include <cuda_runtime.h>

#define BB 64
#define SS 1024
#define DD 16
#define NSPLIT 4
#define TOK (BB * SS)

// Scratch (allocation-free rule: __device__ globals)
__device__ float4 g_kv[TOK];            // (k0,k1,v0,v1) per (b,t)
__device__ float2 g_q[TOK];             // q pre-scaled by 0.25*log2(e)
__device__ float4 g_part[NSPLIT * TOK]; // per-split partial (l, a0, a1, 0)
__device__ float  g_W123[256];          // W1@W2@W3
__device__ float  g_bc[16];             // ((b1@W2)+b2)@W3 + b3

__device__ __forceinline__ float ex2_approx(float x) {
    float y;
    asm("ex2.approx.f32 %0, %1;" : "=f"(y) : "f"(x));
    return y;
}

// ---------------------------------------------------------------------------
// Kernel 0: fold the 3 linear FF layers into one (no nonlinearity between).
// One block of 256 threads: thread (r,c) computes one element.
// ---------------------------------------------------------------------------
__global__ void __launch_bounds__(256)
precomp_kernel(const float* __restrict__ W1, const float* __restrict__ b1,
               const float* __restrict__ W2, const float* __restrict__ b2,
               const float* __restrict__ W3, const float* __restrict__ b3)
{
    __shared__ float s1[256], s2[256], s3[256], s12[256], sb[16];
    int tid = threadIdx.x;
    s1[tid] = W1[tid]; s2[tid] = W2[tid]; s3[tid] = W3[tid];
    __syncthreads();

    int r = tid >> 4, c = tid & 15;
    float acc = 0.f;
    #pragma unroll
    for (int k = 0; k < 16; k++) acc = fmaf(s1[r*16+k], s2[k*16+c], acc);
    s12[tid] = acc;
    if (tid < 16) {           // t = b1@W2 + b2
        float t = b2[tid];
        #pragma unroll
        for (int k = 0; k < 16; k++) t = fmaf(b1[k], s2[k*16+tid], t);
        sb[tid] = t;
    }
    __syncthreads();

    float acc2 = 0.f;
    #pragma unroll
    for (int k = 0; k < 16; k++) acc2 = fmaf(s12[r*16+k], s3[k*16+c], acc2);
    g_W123[tid] = acc2;
    if (tid < 16) {           // bc = t@W3 + b3
        float t = b3[tid];
        #pragma unroll
        for (int k = 0; k < 16; k++) t = fmaf(sb[k], s3[k*16+tid], t);
        g_bc[tid] = t;
    }
}

// ---------------------------------------------------------------------------
// Kernel 1: QKV projection (R1 version: x read once per token).
// ---------------------------------------------------------------------------
__global__ void __launch_bounds__(256)
qkv_kernel(const float* __restrict__ x,
           const float* __restrict__ Wq, const float* __restrict__ bq,
           const float* __restrict__ Wk, const float* __restrict__ bk,
           const float* __restrict__ Wv, const float* __restrict__ bv)
{
    __shared__ float sw[102];
    int tid = threadIdx.x;
    if (tid < 32)        sw[tid] = Wq[tid];
    else if (tid < 64)   sw[tid] = Wk[tid - 32];
    else if (tid < 96)   sw[tid] = Wv[tid - 64];
    else if (tid < 98)   sw[tid] = bq[tid - 96];
    else if (tid < 100)  sw[tid] = bk[tid - 98];
    else if (tid < 102)  sw[tid] = bv[tid - 100];
    __syncthreads();

    int idx = blockIdx.x * 256 + tid;
    const float4* xp = reinterpret_cast<const float4*>(x + idx * DD);
    float xv[16];
    #pragma unroll
    for (int c = 0; c < 4; c++) {
        float4 v = xp[c];
        xv[4*c+0] = v.x; xv[4*c+1] = v.y; xv[4*c+2] = v.z; xv[4*c+3] = v.w;
    }

    float q0 = sw[96], q1 = sw[97];
    float k0 = sw[98], k1 = sw[99];
    float v0 = sw[100], v1 = sw[101];
    #pragma unroll
    for (int i = 0; i < 16; i++) {
        float xi = xv[i];
        q0 = fmaf(xi, sw[i*2+0],    q0);
        q1 = fmaf(xi, sw[i*2+1],    q1);
        k0 = fmaf(xi, sw[32+i*2+0], k0);
        k1 = fmaf(xi, sw[32+i*2+1], k1);
        v0 = fmaf(xi, sw[64+i*2+0], v0);
        v1 = fmaf(xi, sw[64+i*2+1], v1);
    }

    const float SC = 0.25f * 1.4426950408889634f;  // fold scale + log2e into Q
    g_q[idx]  = make_float2(q0 * SC, q1 * SC);
    g_kv[idx] = make_float4(k0, k1, v0, v1);
}

// ---------------------------------------------------------------------------
// Kernel 2: attention with 4-way BLOCK split over KV.
// Grid (S/256, NSPLIT, B); 256 threads = 256 tokens; each block owns a
// 256-token KV quarter (4 KB smem). All lanes broadcast-read one float4
// per iter (conflict-free, 1 wavefront) -- R1 loop shape at 4.6x occupancy.
// ---------------------------------------------------------------------------
__global__ void __launch_bounds__(256)
attn_kernel()
{
    __shared__ float4 skv[256];   // 4 KB quarter

    int tid   = threadIdx.x;
    int b     = blockIdx.z;
    int split = blockIdx.y;
    int s     = blockIdx.x * 256 + tid;

    skv[tid] = g_kv[b * SS + split * 256 + tid];
    __syncthreads();

    float2 q = g_q[b * SS + s];
    float l = 0.f, a0 = 0.f, a1 = 0.f;

    #pragma unroll 8
    for (int t = 0; t < 256; t++) {
        float4 kv = skv[t];
        float d = fmaf(q.y, kv.y, q.x * kv.x);   // log2-domain score
        float p = ex2_approx(d);
        l  += p;
        a0 = fmaf(p, kv.z, a0);
        a1 = fmaf(p, kv.w, a1);
    }

    g_part[split * TOK + b * SS + s] = make_float4(l, a0, a1, 0.f);
}

// ---------------------------------------------------------------------------
__device__ __forceinline__ void mm16(const float* __restrict__ in,
                                     const float* __restrict__ Ws,
                                     const float* __restrict__ bs,
                                     float* __restrict__ outr)
{
    float acc[16];
    #pragma unroll
    for (int j = 0; j < 16; j++) acc[j] = bs[j];
    #pragma unroll
    for (int i = 0; i < 16; i++) {
        float hv = in[i];
        const float4* wr = reinterpret_cast<const float4*>(Ws + i * 16);
        #pragma unroll
        for (int j = 0; j < 4; j++) {
            float4 w = wr[j];
            acc[4*j+0] = fmaf(hv, w.x, acc[4*j+0]);
            acc[4*j+1] = fmaf(hv, w.y, acc[4*j+1]);
            acc[4*j+2] = fmaf(hv, w.z, acc[4*j+2]);
            acc[4*j+3] = fmaf(hv, w.w, acc[4*j+3]);
        }
    }
    #pragma unroll
    for (int j = 0; j < 16; j++) outr[j] = acc[j];
}

__device__ __forceinline__ void layernorm16(float* __restrict__ v,
                                            const float* __restrict__ g,
                                            const float* __restrict__ b)
{
    float mu = 0.f;
    #pragma unroll
    for (int j = 0; j < 16; j++) mu += v[j];
    mu *= (1.0f / 16.0f);
    float var = 0.f;
    #pragma unroll
    for (int j = 0; j < 16; j++) { float d = v[j] - mu; var = fmaf(d, d, var); }
    var *= (1.0f / 16.0f);
    float r = rsqrtf(var + 1e-5f);
    #pragma unroll
    for (int j = 0; j < 16; j++) v[j] = fmaf((v[j] - mu) * r, g[j], b[j]);
}

// ---------------------------------------------------------------------------
// Kernel 3: combine partials + Wu + residual + LN + fused-FF + LN + Wo.
// ---------------------------------------------------------------------------
__global__ void __launch_bounds__(128)
epilogue_kernel(const float* __restrict__ x,
                const float* __restrict__ Wu, const float* __restrict__ bu,
                const float* __restrict__ ln_g, const float* __restrict__ ln_b,
                const float* __restrict__ Wo, const float* __restrict__ bo,
                float* __restrict__ out)
{
    __shared__ __align__(16) float sWf[256], sWo[256], sWu[32];
    __shared__ float sbu[16], sg[16], sb[16], sbc[16], sbo[16];

    int tid = threadIdx.x;
    int idx = blockIdx.x * 128 + tid;

    for (int i = tid; i < 256; i += 128) { sWf[i] = g_W123[i]; sWo[i] = Wo[i]; }
    if (tid < 32) sWu[tid] = Wu[tid];
    if (tid < 16) {
        sbu[tid] = bu[tid]; sg[tid] = ln_g[tid]; sb[tid] = ln_b[tid];
        sbc[tid] = g_bc[tid]; sbo[tid] = bo[tid];
    }
    __syncthreads();

    // Combine the 4 KV-split partials
    float l = 0.f, a0 = 0.f, a1 = 0.f;
    #pragma unroll
    for (int sp = 0; sp < NSPLIT; sp++) {
        float4 p = g_part[sp * TOK + idx];
        l += p.x; a0 += p.y; a1 += p.z;
    }
    float inv = 1.0f / l;
    float c0 = a0 * inv, c1 = a1 * inv;

    float xr[16];
    const float4* xp = reinterpret_cast<const float4*>(x + idx * DD);
    #pragma unroll
    for (int ci = 0; ci < 4; ci++) {
        float4 v = xp[ci];
        xr[4*ci+0] = v.x; xr[4*ci+1] = v.y; xr[4*ci+2] = v.z; xr[4*ci+3] = v.w;
    }

    float h[16];
    #pragma unroll
    for (int j = 0; j < 16; j++)
        h[j] = fmaf(c0, sWu[j], fmaf(c1, sWu[16 + j], sbu[j])) + xr[j];

    layernorm16(h, sg, sb);

    // ff = h @ (W1W2W3) + bc, residual, LN
    float t3[16];
    mm16(h, sWf, sbc, t3);
    #pragma unroll
    for (int j = 0; j < 16; j++) t3[j] += h[j];

    layernorm16(t3, sg, sb);

    float o[16];
    mm16(t3, sWo, sbo, o);

    float4* op = reinterpret_cast<float4*>(out + idx * DD);
    #pragma unroll
    for (int ci = 0; ci < 4; ci++)
        op[ci] = make_float4(o[4*ci+0], o[4*ci+1], o[4*ci+2], o[4*ci+3]);
}

// ---------------------------------------------------------------------------
extern "C" void kernel_launch(void* const* d_in, const int* in_sizes, int n_in,
                              void* d_out, int out_size)
{
    const float* x    = (const float*)d_in[0];
    const float* Wq   = (const float*)d_in[1];
    const float* bq   = (const float*)d_in[2];
    const float* Wk   = (const float*)d_in[3];
    const float* bk   = (const float*)d_in[4];
    const float* Wv   = (const float*)d_in[5];
    const float* bv   = (const float*)d_in[6];
    const float* Wu   = (const float*)d_in[7];
    const float* bu   = (const float*)d_in[8];
    const float* ln_g = (const float*)d_in[9];
    const float* ln_b = (const float*)d_in[10];
    const float* W1   = (const float*)d_in[11];
    const float* b1   = (const float*)d_in[12];
    const float* W2   = (const float*)d_in[13];
    const float* b2   = (const float*)d_in[14];
    const float* W3   = (const float*)d_in[15];
    const float* b3   = (const float*)d_in[16];
    const float* Wo   = (const float*)d_in[17];
    const float* bo   = (const float*)d_in[18];
    float* out = (float*)d_out;

    precomp_kernel<<<1, 256>>>(W1, b1, W2, b2, W3, b3);

    qkv_kernel<<<TOK / 256, 256>>>(x, Wq, bq, Wk, bk, Wv, bv);

    dim3 agrid(SS / 256, NSPLIT, BB);
    attn_kernel<<<agrid, 256>>>();

    epilogue_kernel<<<TOK / 128, 128>>>(x, Wu, bu, ln_g, ln_b, Wo, bo, out);
}

// round 5
// speedup vs baseline: 3.8955x; 1.0077x over previous
#include <cuda_runtime.h>

#define BB 64
#define SS 1024
#define DD 16
#define NSPLIT 4
#define TOK (BB * SS)

// Scratch (allocation-free rule: __device__ globals)
__device__ float4 g_kv[TOK];            // (k0,k1,v0,v1) per (b,t)
__device__ float2 g_q[TOK];             // q pre-scaled by 0.25*log2(e)
__device__ float4 g_part[NSPLIT * TOK]; // per-split partial (l, a0, a1, 0)
__device__ float  g_W123[256];          // W1@W2@W3
__device__ float  g_bc[16];             // ((b1@W2)+b2)@W3 + b3

__device__ __forceinline__ float ex2_approx(float x) {
    float y;
    asm("ex2.approx.f32 %0, %1;" : "=f"(y) : "f"(x));
    return y;
}

// ---------------------------------------------------------------------------
// Kernel 1: QKV projection for blocks [0, TOK/256); last block folds the
// 3 linear FF layers into one (W123, bc) -- saves a separate launch.
// ---------------------------------------------------------------------------
__global__ void __launch_bounds__(256)
qkv_precomp_kernel(const float* __restrict__ x,
                   const float* __restrict__ Wq, const float* __restrict__ bq,
                   const float* __restrict__ Wk, const float* __restrict__ bk,
                   const float* __restrict__ Wv, const float* __restrict__ bv,
                   const float* __restrict__ W1, const float* __restrict__ b1,
                   const float* __restrict__ W2, const float* __restrict__ b2,
                   const float* __restrict__ W3, const float* __restrict__ b3)
{
    int tid = threadIdx.x;

    if (blockIdx.x == TOK / 256) {
        // ---- precompute W123 = W1@W2@W3 and bc = ((b1@W2)+b2)@W3+b3 ----
        __shared__ float s1[256], s2[256], s3[256], s12[256], sbp[16];
        s1[tid] = W1[tid]; s2[tid] = W2[tid]; s3[tid] = W3[tid];
        __syncthreads();
        int r = tid >> 4, c = tid & 15;
        float acc = 0.f;
        #pragma unroll
        for (int k = 0; k < 16; k++) acc = fmaf(s1[r*16+k], s2[k*16+c], acc);
        s12[tid] = acc;
        if (tid < 16) {
            float t = b2[tid];
            #pragma unroll
            for (int k = 0; k < 16; k++) t = fmaf(b1[k], s2[k*16+tid], t);
            sbp[tid] = t;
        }
        __syncthreads();
        float acc2 = 0.f;
        #pragma unroll
        for (int k = 0; k < 16; k++) acc2 = fmaf(s12[r*16+k], s3[k*16+c], acc2);
        g_W123[tid] = acc2;
        if (tid < 16) {
            float t = b3[tid];
            #pragma unroll
            for (int k = 0; k < 16; k++) t = fmaf(sbp[k], s3[k*16+tid], t);
            g_bc[tid] = t;
        }
        return;
    }

    // ---- QKV projection: one thread per token ----
    __shared__ float sw[102];
    if (tid < 32)        sw[tid] = Wq[tid];
    else if (tid < 64)   sw[tid] = Wk[tid - 32];
    else if (tid < 96)   sw[tid] = Wv[tid - 64];
    else if (tid < 98)   sw[tid] = bq[tid - 96];
    else if (tid < 100)  sw[tid] = bk[tid - 98];
    else if (tid < 102)  sw[tid] = bv[tid - 100];
    __syncthreads();

    int idx = blockIdx.x * 256 + tid;
    const float4* xp = reinterpret_cast<const float4*>(x + idx * DD);
    float xv[16];
    #pragma unroll
    for (int c = 0; c < 4; c++) {
        float4 v = xp[c];
        xv[4*c+0] = v.x; xv[4*c+1] = v.y; xv[4*c+2] = v.z; xv[4*c+3] = v.w;
    }

    float q0 = sw[96], q1 = sw[97];
    float k0 = sw[98], k1 = sw[99];
    float v0 = sw[100], v1 = sw[101];
    #pragma unroll
    for (int i = 0; i < 16; i++) {
        float xi = xv[i];
        q0 = fmaf(xi, sw[i*2+0],    q0);
        q1 = fmaf(xi, sw[i*2+1],    q1);
        k0 = fmaf(xi, sw[32+i*2+0], k0);
        k1 = fmaf(xi, sw[32+i*2+1], k1);
        v0 = fmaf(xi, sw[64+i*2+0], v0);
        v1 = fmaf(xi, sw[64+i*2+1], v1);
    }

    const float SC = 0.25f * 1.4426950408889634f;  // fold scale + log2e into Q
    g_q[idx]  = make_float2(q0 * SC, q1 * SC);
    g_kv[idx] = make_float4(k0, k1, v0, v1);
}

// ---------------------------------------------------------------------------
// Kernel 2: attention, 4-way block split over KV (unchanged from R4; at the
// MUFU floor). Grid (S/256, NSPLIT, B); all lanes broadcast-read one float4.
// ---------------------------------------------------------------------------
__global__ void __launch_bounds__(256)
attn_kernel()
{
    __shared__ float4 skv[256];

    int tid   = threadIdx.x;
    int b     = blockIdx.z;
    int split = blockIdx.y;
    int s     = blockIdx.x * 256 + tid;

    skv[tid] = g_kv[b * SS + split * 256 + tid];
    __syncthreads();

    float2 q = g_q[b * SS + s];
    float l = 0.f, a0 = 0.f, a1 = 0.f;

    #pragma unroll 8
    for (int t = 0; t < 256; t++) {
        float4 kv = skv[t];
        float d = fmaf(q.y, kv.y, q.x * kv.x);   // log2-domain score
        float p = ex2_approx(d);
        l  += p;
        a0 = fmaf(p, kv.z, a0);
        a1 = fmaf(p, kv.w, a1);
    }

    g_part[split * TOK + b * SS + s] = make_float4(l, a0, a1, 0.f);
}

// ---------------------------------------------------------------------------
// Distributed helpers: 4 threads per token, each owns 4 of 16 elements.
// ---------------------------------------------------------------------------
__device__ __forceinline__ void ln4(float v[4], const float* __restrict__ g,
                                    const float* __restrict__ b, int q)
{
    float s = (v[0] + v[1]) + (v[2] + v[3]);
    s += __shfl_xor_sync(0xFFFFFFFFu, s, 1);
    s += __shfl_xor_sync(0xFFFFFFFFu, s, 2);
    float mu = s * (1.0f / 16.0f);
    float var = 0.f;
    #pragma unroll
    for (int j = 0; j < 4; j++) { float d = v[j] - mu; var = fmaf(d, d, var); }
    var += __shfl_xor_sync(0xFFFFFFFFu, var, 1);
    var += __shfl_xor_sync(0xFFFFFFFFu, var, 2);
    float r = rsqrtf(var * (1.0f / 16.0f) + 1e-5f);
    #pragma unroll
    for (int j = 0; j < 4; j++)
        v[j] = fmaf((v[j] - mu) * r, g[q*4+j], b[q*4+j]);
}

// outq[j] = bias[q*4+j] + sum_i in[i] * Ws[i*16 + q*4 + j], input distributed.
__device__ __forceinline__ void mm16q(const float hq[4],
                                      const float* __restrict__ Ws,
                                      const float* __restrict__ bs,
                                      int q, float outq[4])
{
    float a0 = bs[q*4+0], a1 = bs[q*4+1], a2 = bs[q*4+2], a3 = bs[q*4+3];
    #pragma unroll
    for (int i = 0; i < 16; i++) {
        float hv = __shfl_sync(0xFFFFFFFFu, hq[i & 3], i >> 2, 4);
        float4 w = *reinterpret_cast<const float4*>(Ws + i * 16 + q * 4);
        a0 = fmaf(hv, w.x, a0);
        a1 = fmaf(hv, w.y, a1);
        a2 = fmaf(hv, w.z, a2);
        a3 = fmaf(hv, w.w, a3);
    }
    outq[0] = a0; outq[1] = a1; outq[2] = a2; outq[3] = a3;
}

// ---------------------------------------------------------------------------
// Kernel 3: epilogue, 4 threads per token (262144 threads).
// ---------------------------------------------------------------------------
__global__ void __launch_bounds__(256)
epilogue_kernel(const float* __restrict__ x,
                const float* __restrict__ Wu, const float* __restrict__ bu,
                const float* __restrict__ ln_g, const float* __restrict__ ln_b,
                const float* __restrict__ Wo, const float* __restrict__ bo,
                float* __restrict__ out)
{
    __shared__ __align__(16) float sWf[256], sWo[256], sWu[32];
    __shared__ float sbu[16], sg[16], sb[16], sbc[16], sbo[16];

    int tid = threadIdx.x;
    int token = blockIdx.x * 64 + (tid >> 2);
    int q = tid & 3;

    if (tid < 256) { sWf[tid] = g_W123[tid]; sWo[tid] = Wo[tid]; }
    if (tid < 32) sWu[tid] = Wu[tid];
    if (tid < 16) {
        sbu[tid] = bu[tid]; sg[tid] = ln_g[tid]; sb[tid] = ln_b[tid];
        sbc[tid] = g_bc[tid]; sbo[tid] = bo[tid];
    }
    __syncthreads();

    // Combine partials: lane q reads split q
    float4 p = g_part[q * TOK + token];
    float l = p.x, a0 = p.y, a1 = p.z;
    l  += __shfl_xor_sync(0xFFFFFFFFu, l, 1);
    a0 += __shfl_xor_sync(0xFFFFFFFFu, a0, 1);
    a1 += __shfl_xor_sync(0xFFFFFFFFu, a1, 1);
    l  += __shfl_xor_sync(0xFFFFFFFFu, l, 2);
    a0 += __shfl_xor_sync(0xFFFFFFFFu, a0, 2);
    a1 += __shfl_xor_sync(0xFFFFFFFFu, a1, 2);
    float inv = 1.0f / l;
    float c0 = a0 * inv, c1 = a1 * inv;

    // h quarter = ctx @ Wu + bu + x
    float4 xv = reinterpret_cast<const float4*>(x)[token * 4 + q];
    float h[4];
    h[0] = fmaf(c0, sWu[q*4+0], fmaf(c1, sWu[16+q*4+0], sbu[q*4+0])) + xv.x;
    h[1] = fmaf(c0, sWu[q*4+1], fmaf(c1, sWu[16+q*4+1], sbu[q*4+1])) + xv.y;
    h[2] = fmaf(c0, sWu[q*4+2], fmaf(c1, sWu[16+q*4+2], sbu[q*4+2])) + xv.z;
    h[3] = fmaf(c0, sWu[q*4+3], fmaf(c1, sWu[16+q*4+3], sbu[q*4+3])) + xv.w;

    ln4(h, sg, sb, q);

    float t[4];
    mm16q(h, sWf, sbc, q, t);
    #pragma unroll
    for (int j = 0; j < 4; j++) t[j] += h[j];

    ln4(t, sg, sb, q);

    float o[4];
    mm16q(t, sWo, sbo, q, o);

    reinterpret_cast<float4*>(out)[token * 4 + q] =
        make_float4(o[0], o[1], o[2], o[3]);
}

// ---------------------------------------------------------------------------
extern "C" void kernel_launch(void* const* d_in, const int* in_sizes, int n_in,
                              void* d_out, int out_size)
{
    const float* x    = (const float*)d_in[0];
    const float* Wq   = (const float*)d_in[1];
    const float* bq   = (const float*)d_in[2];
    const float* Wk   = (const float*)d_in[3];
    const float* bk   = (const float*)d_in[4];
    const float* Wv   = (const float*)d_in[5];
    const float* bv   = (const float*)d_in[6];
    const float* Wu   = (const float*)d_in[7];
    const float* bu   = (const float*)d_in[8];
    const float* ln_g = (const float*)d_in[9];
    const float* ln_b = (const float*)d_in[10];
    const float* W1   = (const float*)d_in[11];
    const float* b1   = (const float*)d_in[12];
    const float* W2   = (const float*)d_in[13];
    const float* b2   = (const float*)d_in[14];
    const float* W3   = (const float*)d_in[15];
    const float* b3   = (const float*)d_in[16];
    const float* Wo   = (const float*)d_in[17];
    const float* bo   = (const float*)d_in[18];
    float* out = (float*)d_out;

    qkv_precomp_kernel<<<TOK / 256 + 1, 256>>>(x, Wq, bq, Wk, bk, Wv, bv,
                                               W1, b1, W2, b2, W3, b3);

    dim3 agrid(SS / 256, NSPLIT, BB);
    attn_kernel<<<agrid, 256>>>();

    epilogue_kernel<<<TOK / 64, 256>>>(x, Wu, bu, ln_g, ln_b, Wo, bo, out);
}